// round 16
// baseline (speedup 1.0000x reference)
#include <cuda_runtime.h>
#include <cuda_fp16.h>
#include <cstdint>

// Conv as implicit GEMM, single-pass fp16 (fp32 acc), tap-decomposed K.
// K order: k = (r*3+s)*128 + c, BK=64 = half tap -> 18 chunks.
// NEW: A (weights) is fed to mma.sync directly from registers via LDG.64 from a
// fragment-permuted layout (per c16 group store order 0,1,8,9,2,3,10,11,...),
// bypassing smem/L1 entirely for A. Smem holds only B (3-stage cp.async ring).
// CTA 128(oc) x 64(pix), 128 threads (2Mx2N warps, 64x32), 4 CTAs/SM.

#define C_IN   128
#define HWI    3136
#define NPIX   100352
#define KDIM   1152
#define BK     64
#define NCHUNK 18
#define PITCH  144        // B smem row pitch bytes (128B data + 16 pad)

#define STAGE_B 9216      // 64 * 144
#define NSTAGE  3
#define SMEM_TOTAL (NSTAGE * STAGE_B)   // 27648 (static)

__device__ __align__(16) __half g_wh[256 * KDIM];                 // [oc][tap-major, perm c16]
__device__ __align__(16) __half g_xh[(size_t)32 * HWI * C_IN];    // NHWC fp16, 51MB

static __device__ __forceinline__ uint32_t s2u(const void* p) {
    uint32_t a;
    asm("{ .reg .u64 t; cvta.to.shared.u64 t, %1; cvt.u32.u64 %0, t; }" : "=r"(a) : "l"(p));
    return a;
}

static __device__ __forceinline__ void cp16z(uint32_t dst, const void* src, uint32_t src_sz) {
    asm volatile("cp.async.cg.shared.global [%0], [%1], 16, %2;"
                 :: "r"(dst), "l"(src), "r"(src_sz));
}

static __device__ __forceinline__ void ldsm4(uint32_t* r, uint32_t addr) {
    asm volatile("ldmatrix.sync.aligned.m8n8.x4.shared.b16 {%0,%1,%2,%3}, [%4];"
                 : "=r"(r[0]), "=r"(r[1]), "=r"(r[2]), "=r"(r[3]) : "r"(addr));
}

static __device__ __forceinline__ void mma4(float* c,
                                            uint32_t a0, uint32_t a1, uint32_t a2, uint32_t a3,
                                            uint32_t b0, uint32_t b1) {
    asm volatile(
        "mma.sync.aligned.m16n8k16.row.col.f32.f16.f16.f32 "
        "{%0,%1,%2,%3}, {%4,%5,%6,%7}, {%8,%9}, {%0,%1,%2,%3};"
        : "+f"(c[0]), "+f"(c[1]), "+f"(c[2]), "+f"(c[3])
        : "r"(a0), "r"(a1), "r"(a2), "r"(a3), "r"(b0), "r"(b1));
}

static __device__ __forceinline__ uint2 ldg64(const __half* p) {
    return __ldg((const uint2*)p);
}

// perm within a c16 group: positions (q) -> orig c offset
// q: 0,1 -> 0,1 | 2,3 -> 8,9 | 4,5 -> 2,3 | 6,7 -> 10,11 | 8.. -> 4,5,12,13,6,7,14,15
static __host__ __device__ __forceinline__ int permq(int q) {
    return 2 * (q >> 2) + (q & 1) + ((q & 2) ? 8 : 0);
}

// ---------- pre-kernel 1: weights fp32 -> fp16, k=(tap)*128+c with c16 fragment perm ----------
__global__ void prep_w(const float* __restrict__ w) {
    const int gid = blockIdx.x * 256 + threadIdx.x;   // 36864 = 256 oc x 144 segs
    const int oc = gid / 144;
    const int j  = gid - oc * 144;                    // 8-half output segment
    const int p0    = j * 8;                          // perm-layout position
    const int tap   = p0 >> 7;
    const int cpos0 = p0 & 127;
    const int g     = cpos0 >> 4;                     // c16 group
    const int qb    = cpos0 & 15;                     // 0 or 8
    __half h[8];
    #pragma unroll
    for (int e = 0; e < 8; ++e) {
        const int c = g * 16 + permq(qb + e);
        h[e] = __float2half_rn(w[oc * KDIM + c * 9 + tap]);
    }
    *(uint4*)&g_wh[oc * KDIM + j * 8] = *(uint4*)h;
}

// ---------- pre-kernel 2: x fp32 NCHW -> fp16 NHWC (smem transpose) ----------
__global__ void prep_nhwc(const float* __restrict__ x) {
    __shared__ __half sm[64][136];                    // 272B pitch: 16B-aligned reads
    const int hw0 = blockIdx.x * 64;
    const int n   = blockIdx.y;
    const int tid = threadIdx.x;
    const int c4  = tid >> 6;
    const int hwi = tid & 63;
    const float* __restrict__ xn = x + (size_t)n * C_IN * HWI;
    #pragma unroll
    for (int cc = 0; cc < 32; ++cc) {
        const int c = c4 * 32 + cc;
        sm[hwi][c] = __float2half_rn(xn[(size_t)c * HWI + hw0 + hwi]);
    }
    __syncthreads();
    const int row  = tid >> 2;
    const int part = tid & 3;
    __half* dst = &g_xh[((size_t)(n * HWI + hw0 + row)) * C_IN + part * 32];
    const __half* srcp = &sm[row][part * 32];
    #pragma unroll
    for (int q = 0; q < 4; ++q)
        *(uint4*)(dst + q * 8) = *(const uint4*)(srcp + q * 8);
}

// ---------- main GEMM kernel ----------
__global__ __launch_bounds__(128, 4)
void conv_main(const float* __restrict__ bias, float* __restrict__ out)
{
    __shared__ __align__(16) char smem[SMEM_TOTAL];   // B-only 3-stage ring
    const uint32_t sb = s2u(smem);

    const int tid  = threadIdx.x;
    const int lane = tid & 31;
    const int wid  = tid >> 5;
    const int oc0  = blockIdx.x * 128;
    const int pix0 = blockIdx.y * 64;

    const int wm = wid & 1;       // M: 2 x 64
    const int wn = wid >> 1;      // N: 2 x 32

    // ---- B fill chores: 512 x 16B -> 4 per thread ----
    const int rowF = tid >> 3;    // 0..15
    const int segF = tid & 7;
    uint32_t bDst[4];
    const char* bBase[4];
    int bOh[4], bOw[4];
    #pragma unroll
    for (int i = 0; i < 4; ++i) {
        const int row = rowF + 16 * i;       // 0..63
        bDst[i] = (uint32_t)(row * PITCH + segF * 16);
        const int pg = pix0 + row;
        const int n  = pg / HWI;
        const int hw = pg - n * HWI;
        bOh[i] = hw / 56;
        bOw[i] = hw - bOh[i] * 56;
        bBase[i] = (const char*)g_xh + ((size_t)n * HWI * C_IN + segF * 8) * 2;
    }

    // ---- A fragment base pointers (perm layout: 8 contiguous bytes per pair) ----
    const __half* pA  = g_wh + (size_t)(oc0 + wm * 64 + (lane >> 2)) * KDIM + (lane & 3) * 4;
    const __half* pA8 = pA + 8 * KDIM;

    // ---- B ldmatrix lane addressing ----
    const int bRow = ((lane >> 4) << 3) | (lane & 7);
    const int bSel = (lane >> 3) & 1;
    const uint32_t bOffB = (uint32_t)((wn * 32 + bRow) * PITCH + bSel * 16);

    float acc[4][4][4];
    #pragma unroll
    for (int i = 0; i < 4; i++)
        #pragma unroll
        for (int j = 0; j < 4; j++)
            #pragma unroll
            for (int q = 0; q < 4; q++)
                acc[i][j][q] = 0.0f;

    // ---- fill one stage with chunk ck's B tile ----
    auto fill_stage = [&](int ck, uint32_t st) {
        const int tp  = ck >> 1;
        const int fr  = (tp * 11) >> 5;           // tp/3 for tp<9
        const int fs  = tp - fr * 3;
        const int fc0 = (ck & 1) * 64;
        #pragma unroll
        for (int i = 0; i < 4; ++i) {
            const int ih = bOh[i] + fr - 1;
            const int iw = bOw[i] + fs - 1;
            const uint32_t ok = ((unsigned)ih < 56u && (unsigned)iw < 56u) ? 16u : 0u;
            const char* src = bBase[i] + ((ptrdiff_t)(ih * 56 + iw) * C_IN + fc0) * 2;
            cp16z(st + bDst[i], src, ok);
        }
        asm volatile("cp.async.commit_group;" ::: "memory");
    };

    auto stage_of = [&](int ck) { return sb + (uint32_t)((ck % 3) * STAGE_B); };

    // ---- prologue: fill chunks 0,1; preload first A pair ----
    fill_stage(0, stage_of(0));
    fill_stage(1, stage_of(1));
    uint2 aP0 = ldg64(pA);
    uint2 aP1 = ldg64(pA8);

    #pragma unroll 1
    for (int chunk = 0; chunk < NCHUNK; ++chunk) {
        asm volatile("cp.async.wait_group %0;" :: "n"(NSTAGE - 2) : "memory");
        __syncthreads();

        // ---- issue chunk+2's B into just-freed stage ----
        {
            const int cn = chunk + NSTAGE - 1;
            if (cn < NCHUNK) {
                fill_stage(cn, stage_of(cn));
            } else {
                asm volatile("cp.async.commit_group;" ::: "memory");
            }
        }

        // ---- MMA: 4 k16 steps x (4M x 4N); A via LDG.64 one-step prefetch ----
        const uint32_t bufS = stage_of(chunk);
        const int cOff = chunk * 64;
        #pragma unroll
        for (int ks = 0; ks < 4; ++ks) {
            const uint32_t ko = (uint32_t)(ks * 32);
            uint32_t bf[8];
            ldsm4(&bf[0], bufS + bOffB + ko);
            ldsm4(&bf[4], bufS + bOffB + ko + 16 * PITCH);
            #pragma unroll
            for (int mt = 0; mt < 4; ++mt) {
                const uint32_t a0 = aP0.x, a2 = aP0.y;
                const uint32_t a1 = aP1.x, a3 = aP1.y;
                // prefetch next A pair
                int off;
                if (mt < 3)        off = (mt + 1) * 16 * KDIM + cOff + ks * 16;
                else if (ks < 3)   off = cOff + (ks + 1) * 16;
                else               off = (chunk + 1 < NCHUNK) ? (chunk + 1) * 64 : 0;
                aP0 = ldg64(pA  + off);
                aP1 = ldg64(pA8 + off);
                mma4(acc[mt][0], a0, a1, a2, a3, bf[0], bf[1]);
                mma4(acc[mt][1], a0, a1, a2, a3, bf[2], bf[3]);
                mma4(acc[mt][2], a0, a1, a2, a3, bf[4], bf[5]);
                mma4(acc[mt][3], a0, a1, a2, a3, bf[6], bf[7]);
            }
        }
    }

    // ---- epilogue ----
    #pragma unroll
    for (int mt = 0; mt < 4; ++mt) {
        const int r0 = oc0 + wm * 64 + mt * 16 + (lane >> 2);
        const int r1 = r0 + 8;
        const float bv0 = __ldg(&bias[r0]);
        const float bv1 = __ldg(&bias[r1]);
        #pragma unroll
        for (int nt = 0; nt < 4; ++nt) {
            const int pg   = pix0 + wn * 32 + nt * 8 + (lane & 3) * 2;
            const int nimg = pg / HWI;
            const int hw   = pg - nimg * HWI;
            const float* c = acc[mt][nt];
            float2 v0 = make_float2(c[0] + bv0, c[1] + bv0);
            float2 v1 = make_float2(c[2] + bv1, c[3] + bv1);
            *(float2*)&out[((size_t)nimg * 256 + r0) * HWI + hw] = v0;
            *(float2*)&out[((size_t)nimg * 256 + r1) * HWI + hw] = v1;
        }
    }
}

extern "C" void kernel_launch(void* const* d_in, const int* in_sizes, int n_in,
                              void* d_out, int out_size)
{
    const float* x    = (const float*)d_in[0];   // [32,128,56,56]
    const float* wgt  = (const float*)d_in[1];   // [256,128,3,3]
    const float* bias = (const float*)d_in[2];   // [256]
    float* out        = (float*)d_out;           // [32,256,56,56]

    prep_w<<<144, 256>>>(wgt);
    prep_nhwc<<<dim3(HWI / 64, 32), 256>>>(x);
    dim3 grid(2, NPIX / 64);                     // oc fast -> L2 reuse of B
    conv_main<<<grid, 128>>>(bias, out);
}

// round 17
// speedup vs baseline: 1.6691x; 1.6691x over previous
#include <cuda_runtime.h>
#include <cuda_fp16.h>
#include <cstdint>

// Conv as implicit GEMM, single-pass fp16 (fp32 acc), tap-decomposed K.
// K order: k = (r*3+s)*128 + c. BK=64 = half a tap -> 18 chunks.
// CTA 128(oc) x 64(pix), 128 threads (2Mx2N warps, warp tile 64x32),
// 2-stage cp.async ring, 4 CTAs/SM (best measured config, R14 = 210.9us).
// This round: prep_w merged into prep_nhwc (2 launches/invocation) so ncu's
// "-s 5 -c 1" lands on conv_main instead of prep_w.

#define C_IN   128
#define HWI    3136
#define NPIX   100352
#define KDIM   1152
#define BK     64
#define NCHUNK 18
#define PITCH  144        // smem row pitch bytes (128B data + 16 pad)

#define OFF_A   0
#define OFF_B   18432     // 128*144
#define STAGE_B 27648     // + 64*144
#define NSTAGE  2
#define SMEM_TOTAL (NSTAGE * STAGE_B)   // 55296

#define NBLK_W 144        // prep_w blocks
#define NBLK_X 1568       // prep_nhwc blocks (49 x 32)

__device__ __align__(16) __half g_wh[256 * KDIM];                 // [oc][tap*128+c]
__device__ __align__(16) __half g_xh[(size_t)32 * HWI * C_IN];    // NHWC fp16, 51MB

static __device__ __forceinline__ uint32_t s2u(const void* p) {
    uint32_t a;
    asm("{ .reg .u64 t; cvta.to.shared.u64 t, %1; cvt.u32.u64 %0, t; }" : "=r"(a) : "l"(p));
    return a;
}

static __device__ __forceinline__ void cp16(uint32_t dst, const void* src) {
    asm volatile("cp.async.cg.shared.global [%0], [%1], 16;" :: "r"(dst), "l"(src));
}

static __device__ __forceinline__ void cp16z(uint32_t dst, const void* src, uint32_t src_sz) {
    asm volatile("cp.async.cg.shared.global [%0], [%1], 16, %2;"
                 :: "r"(dst), "l"(src), "r"(src_sz));
}

static __device__ __forceinline__ void ldsm4(uint32_t* r, uint32_t addr) {
    asm volatile("ldmatrix.sync.aligned.m8n8.x4.shared.b16 {%0,%1,%2,%3}, [%4];"
                 : "=r"(r[0]), "=r"(r[1]), "=r"(r[2]), "=r"(r[3]) : "r"(addr));
}

static __device__ __forceinline__ void mma16816(float* c, const uint32_t* a,
                                                uint32_t b0, uint32_t b1) {
    asm volatile(
        "mma.sync.aligned.m16n8k16.row.col.f32.f16.f16.f32 "
        "{%0,%1,%2,%3}, {%4,%5,%6,%7}, {%8,%9}, {%0,%1,%2,%3};"
        : "+f"(c[0]), "+f"(c[1]), "+f"(c[2]), "+f"(c[3])
        : "r"(a[0]), "r"(a[1]), "r"(a[2]), "r"(a[3]), "r"(b0), "r"(b1));
}

// ---------- merged pre-kernel: blocks [0,144) do weights, rest do NHWC ----------
__global__ void prep_all(const float* __restrict__ w, const float* __restrict__ x) {
    __shared__ __half sm[64][136];                    // 272B pitch: 16B-aligned reads
    const int bid = blockIdx.x;
    const int tid = threadIdx.x;

    if (bid < NBLK_W) {
        // ---- weights fp32 -> fp16, reordered to k=(tap)*128+c ----
        const int gid = bid * 256 + tid;              // 36864 = 256 oc x 144 segs
        const int oc = gid / 144;
        const int j  = gid - oc * 144;
        const int tap = j >> 4;
        const int c0  = (j & 15) * 8;
        __half h[8];
        #pragma unroll
        for (int e = 0; e < 8; ++e)
            h[e] = __float2half_rn(w[oc * KDIM + (c0 + e) * 9 + tap]);
        *(uint4*)&g_wh[oc * KDIM + j * 8] = *(uint4*)h;
        return;
    }

    // ---- x fp32 NCHW -> fp16 NHWC (smem transpose) ----
    const int xb  = bid - NBLK_W;
    const int hw0 = (xb % 49) * 64;
    const int n   = xb / 49;
    const int c4  = tid >> 6;
    const int hwi = tid & 63;
    const float* __restrict__ xn = x + (size_t)n * C_IN * HWI;
    #pragma unroll
    for (int cc = 0; cc < 32; ++cc) {
        const int c = c4 * 32 + cc;
        sm[hwi][c] = __float2half_rn(xn[(size_t)c * HWI + hw0 + hwi]);
    }
    __syncthreads();
    const int row  = tid >> 2;
    const int part = tid & 3;
    __half* dst = &g_xh[((size_t)(n * HWI + hw0 + row)) * C_IN + part * 32];
    const __half* srcp = &sm[row][part * 32];
    #pragma unroll
    for (int q = 0; q < 4; ++q)
        *(uint4*)(dst + q * 8) = *(const uint4*)(srcp + q * 8);
}

// ---------- main GEMM kernel (R14, best measured) ----------
__global__ __launch_bounds__(128, 4)
void conv_main(const float* __restrict__ bias, float* __restrict__ out)
{
    extern __shared__ __align__(16) char smem[];
    const uint32_t sb = s2u(smem);

    const int tid  = threadIdx.x;
    const int lane = tid & 31;
    const int wid  = tid >> 5;
    const int oc0  = blockIdx.x * 128;
    const int pix0 = blockIdx.y * 64;

    const int wm = wid & 1;       // M: 2 x 64
    const int wn = wid >> 1;      // N: 2 x 32

    // ---- fill chores ----
    const int rowA = tid >> 3;
    const int segA = tid & 7;
    const uint32_t aDst0 = (uint32_t)(rowA * PITCH + segA * 16);
    const char* aSrc0 = (const char*)g_wh + ((size_t)(oc0 + rowA) * KDIM + segA * 8) * 2;

    uint32_t bDst[4];
    const char* bBase[4];
    int bOh[4], bOw[4];
    #pragma unroll
    for (int i = 0; i < 4; ++i) {
        const int row = rowA + 16 * i;       // 0..63
        bDst[i] = (uint32_t)(row * PITCH + segA * 16);
        const int pg = pix0 + row;
        const int n  = pg / HWI;
        const int hw = pg - n * HWI;
        bOh[i] = hw / 56;
        bOw[i] = hw - bOh[i] * 56;
        bBase[i] = (const char*)g_xh + ((size_t)n * HWI * C_IN + segA * 8) * 2;
    }

    // ---- ldmatrix lane addressing ----
    const uint32_t aOffB = (uint32_t)((wm * 64 + (lane & 15)) * PITCH + (lane >> 4) * 16);
    const int bRow = ((lane >> 4) << 3) | (lane & 7);
    const int bSel = (lane >> 3) & 1;
    const uint32_t bOffB = (uint32_t)((wn * 32 + bRow) * PITCH + bSel * 16);

    float acc[4][4][4];
    #pragma unroll
    for (int i = 0; i < 4; i++)
        #pragma unroll
        for (int j = 0; j < 4; j++)
            #pragma unroll
            for (int q = 0; q < 4; q++)
                acc[i][j][q] = 0.0f;

    // ---- fill one stage with chunk ck (BK=64 = half tap) ----
    auto fill_stage = [&](int ck, uint32_t st) {
        const int tp  = ck >> 1;
        const int fr  = (tp * 11) >> 5;           // tp/3 for tp<9
        const int fs  = tp - fr * 3;
        const int fc0 = (ck & 1) * 64;
        const uint64_t kB = (uint64_t)ck * BK * 2;
        #pragma unroll
        for (int i = 0; i < 8; ++i)
            cp16(st + OFF_A + aDst0 + (uint32_t)(i * 16 * PITCH),
                 aSrc0 + kB + (size_t)i * 16 * KDIM * 2);
        #pragma unroll
        for (int i = 0; i < 4; ++i) {
            const int ih = bOh[i] + fr - 1;
            const int iw = bOw[i] + fs - 1;
            const uint32_t ok = ((unsigned)ih < 56u && (unsigned)iw < 56u) ? 16u : 0u;
            const char* src = bBase[i] + ((ptrdiff_t)(ih * 56 + iw) * C_IN + fc0) * 2;
            cp16z(st + OFF_B + bDst[i], src, ok);
        }
        asm volatile("cp.async.commit_group;" ::: "memory");
    };

    // ---- prologue: fill stage 0 with chunk 0 ----
    fill_stage(0, sb);

    #pragma unroll 1
    for (int chunk = 0; chunk < NCHUNK; ++chunk) {
        asm volatile("cp.async.wait_group 0;" ::: "memory");
        __syncthreads();

        // ---- issue chunk+1 into the other stage (freed by the barrier) ----
        if (chunk + 1 < NCHUNK)
            fill_stage(chunk + 1, sb + (uint32_t)(((chunk + 1) & 1) * STAGE_B));

        // ---- MMA from stage chunk%2: 4 k16 steps x (4M x 4N tiles) ----
        const uint32_t bufS = sb + (uint32_t)((chunk & 1) * STAGE_B);
        #pragma unroll
        for (int ks = 0; ks < 4; ++ks) {
            const uint32_t ko = (uint32_t)(ks * 32);
            uint32_t bf[8];
            #pragma unroll
            for (int nb = 0; nb < 2; ++nb)
                ldsm4(&bf[nb * 4], bufS + OFF_B + bOffB + ko + (uint32_t)(nb * 16 * PITCH));
            uint32_t af[16];
            #pragma unroll
            for (int mt = 0; mt < 4; ++mt)
                ldsm4(&af[mt * 4], bufS + OFF_A + aOffB + ko + (uint32_t)(mt * 16 * PITCH));
            #pragma unroll
            for (int mt = 0; mt < 4; ++mt)
                #pragma unroll
                for (int nt = 0; nt < 4; ++nt)
                    mma16816(acc[mt][nt], &af[mt * 4], bf[nt * 2], bf[nt * 2 + 1]);
        }
    }

    // ---- epilogue ----
    #pragma unroll
    for (int mt = 0; mt < 4; ++mt) {
        const int r0 = oc0 + wm * 64 + mt * 16 + (lane >> 2);
        const int r1 = r0 + 8;
        const float bv0 = __ldg(&bias[r0]);
        const float bv1 = __ldg(&bias[r1]);
        #pragma unroll
        for (int nt = 0; nt < 4; ++nt) {
            const int pg   = pix0 + wn * 32 + nt * 8 + (lane & 3) * 2;
            const int nimg = pg / HWI;
            const int hw   = pg - nimg * HWI;
            const float* c = acc[mt][nt];
            float2 v0 = make_float2(c[0] + bv0, c[1] + bv0);
            float2 v1 = make_float2(c[2] + bv1, c[3] + bv1);
            *(float2*)&out[((size_t)nimg * 256 + r0) * HWI + hw] = v0;
            *(float2*)&out[((size_t)nimg * 256 + r1) * HWI + hw] = v1;
        }
    }
}

extern "C" void kernel_launch(void* const* d_in, const int* in_sizes, int n_in,
                              void* d_out, int out_size)
{
    const float* x    = (const float*)d_in[0];   // [32,128,56,56]
    const float* wgt  = (const float*)d_in[1];   // [256,128,3,3]
    const float* bias = (const float*)d_in[2];   // [256]
    float* out        = (float*)d_out;           // [32,256,56,56]

    cudaFuncSetAttribute(conv_main,
                         cudaFuncAttributeMaxDynamicSharedMemorySize, SMEM_TOTAL);

    prep_all<<<NBLK_W + NBLK_X, 256>>>(wgt, x);
    dim3 grid(2, NPIX / 64);                     // oc fast -> L2 reuse of B
    conv_main<<<grid, 128, SMEM_TOTAL>>>(bias, out);
}